// round 3
// baseline (speedup 1.0000x reference)
#include <cuda_runtime.h>
#include <cstdint>
#include <cstddef>

// Problem constants
#define BATCH 16384
#define F 512
#define NCTA 64          // scan CTAs; 64 <= 148 SMs -> all co-resident, spin-safe
#define TPB 256          // 8 warps; warp w owns column b*8+w

// Scratch (device globals: no allocation allowed in kernel_launch)
__device__ float g_xwz[(size_t)BATCH * F];                 // x@Wz + bz
__device__ float g_xwh[(size_t)BATCH * F];                 // x@Wh + bh
// (epoch,value) state words: slot t&1, epoch field = t+1, value = m_t[col]
__device__ unsigned long long g_sv[2][F];

// ---------------------------------------------------------------------------
// Zero the state words each launch (epochs persist across graph replays).
// ---------------------------------------------------------------------------
__global__ void zero_state_kernel() {
    int i = blockIdx.x * blockDim.x + threadIdx.x;   // 0..1023
    ((unsigned long long*)g_sv)[i] = 0ull;
}

// ---------------------------------------------------------------------------
// Phase 1: batched GEMM  C = A(16384x512) * W(512x512) + bias
// blockIdx.z = 0 -> (Wz,bz)->g_xwz ; 1 -> (Wh,bh)->g_xwh
// ---------------------------------------------------------------------------
#define BM 64
#define BN 64
#define BKK 16

__global__ void __launch_bounds__(256) gemm_kernel(
    const float* __restrict__ A,
    const float* __restrict__ Wz, const float* __restrict__ bz,
    const float* __restrict__ Wh, const float* __restrict__ bh)
{
    const float* B    = (blockIdx.z == 0) ? Wz : Wh;
    const float* bias = (blockIdx.z == 0) ? bz : bh;
    float*       C    = (blockIdx.z == 0) ? g_xwz : g_xwh;

    __shared__ float As[BKK][BM];
    __shared__ float Bs[BKK][BN];

    const int row0 = blockIdx.y * BM;
    const int col0 = blockIdx.x * BN;
    const int tid  = threadIdx.x;

    const int a_m = tid >> 2;
    const int a_k = (tid & 3) * 4;
    const int b_k = tid >> 4;
    const int b_n = (tid & 15) * 4;

    const int ty = tid >> 4;
    const int tx = tid & 15;

    float acc[4][4] = {};

    for (int k0 = 0; k0 < F; k0 += BKK) {
        float4 av = *(const float4*)(A + (size_t)(row0 + a_m) * F + k0 + a_k);
        As[a_k + 0][a_m] = av.x;
        As[a_k + 1][a_m] = av.y;
        As[a_k + 2][a_m] = av.z;
        As[a_k + 3][a_m] = av.w;
        float4 bv = *(const float4*)(B + (size_t)(k0 + b_k) * F + col0 + b_n);
        *(float4*)&Bs[b_k][b_n] = bv;
        __syncthreads();
#pragma unroll
        for (int k = 0; k < BKK; k++) {
            float ar[4], br[4];
            *(float4*)ar = *(const float4*)&As[k][ty * 4];
            *(float4*)br = *(const float4*)&Bs[k][tx * 4];
#pragma unroll
            for (int i = 0; i < 4; i++)
#pragma unroll
                for (int jj = 0; jj < 4; jj++)
                    acc[i][jj] = fmaf(ar[i], br[jj], acc[i][jj]);
        }
        __syncthreads();
    }

    float4 bv;
    bv.x = __ldg(&bias[col0 + tx * 4 + 0]);
    bv.y = __ldg(&bias[col0 + tx * 4 + 1]);
    bv.z = __ldg(&bias[col0 + tx * 4 + 2]);
    bv.w = __ldg(&bias[col0 + tx * 4 + 3]);
#pragma unroll
    for (int i = 0; i < 4; i++) {
        float4 o;
        o.x = acc[i][0] + bv.x;
        o.y = acc[i][1] + bv.y;
        o.z = acc[i][2] + bv.z;
        o.w = acc[i][3] + bv.w;
        *(float4*)(C + (size_t)(row0 + ty * 4 + i) * F + col0 + tx * 4) = o;
    }
}

// ---------------------------------------------------------------------------
// Phase 2: sequential gated scan, fence-free (epoch,value)-word protocol.
// 64 CTAs x 256 threads. CTA b owns columns b*8..b*8+7 (one per warp).
// Lane l of each warp holds U rows l*16..l*16+15 of its column in registers.
// Per step: warp 0 polls all 512 state words (16 u64/lane, relaxed gpu-scope),
// stages the 512 floats into smem (double-buffered by t&1); one __syncthreads;
// every warp reads its 16 rows from smem, FMAs against register U, butterfly-
// reduces, lane 0 applies the gate and publishes one relaxed 8B (epoch,value)
// word. No atomics, no fences. Aligned 8B relaxed stores are single-copy
// atomic -> data rides with the flag.
//
// Safety of the single mid-step barrier (no trailing barrier): warp 0
// rewrites sbuf[t&1] only at step t+2, reachable only after its poll saw all
// columns of step t+1 -- including this CTA's own, published by warps that
// had already finished reading sbuf[t&1] at step t.
// ---------------------------------------------------------------------------
__global__ void __launch_bounds__(TPB, 1) scan_kernel(
    const float* __restrict__ Uz,
    const float* __restrict__ Uh,
    float* __restrict__ out)
{
    __shared__ float sbuf[2][F];

    const int b = blockIdx.x;
    const int w = threadIdx.x >> 5;
    const int l = threadIdx.x & 31;
    const int j = b * 8 + w;           // global column 0..511
    const int rbase = l * 16;          // first state row for this lane

    // Preload U slices into registers (32 floats/thread, 2MB chip-wide)
    float uz[16], uh[16];
#pragma unroll
    for (int i = 0; i < 16; i++) {
        uz[i] = Uz[(size_t)(rbase + i) * F + j];
        uh[i] = Uh[(size_t)(rbase + i) * F + j];
    }

    // ---- t = 0: m_prev = 0 ----
    if (l == 0) {
        float xz = __ldg(&g_xwz[j]);
        float xh = __ldg(&g_xwh[j]);
        float z = __fdividef(1.f, 1.f + __expf(-xz));
        float h = 1.f - __fdividef(2.f, __expf(2.f * xh) + 1.f);
        float mn = z * h;
        unsigned long long pack =
            (1ull << 32) | (unsigned long long)__float_as_uint(mn);
        asm volatile("st.relaxed.gpu.global.u64 [%0], %1;"
                     :: "l"(&g_sv[0][j]), "l"(pack) : "memory");
        out[j] = mn;
    }

    for (int t = 1; t < BATCH; t++) {
        // Prefetch x@W terms (independent of recurrence; overlaps the poll)
        float xz = 0.f, xh = 0.f;
        if (l == 0) {
            xz = __ldg(&g_xwz[(size_t)t * F + j]);
            xh = __ldg(&g_xwh[(size_t)t * F + j]);
        }

        const int sl = (t - 1) & 1;    // slot holding m_{t-1}
        const int sb = t & 1;          // smem staging buffer for this step

        if (w == 0) {
            const unsigned long long* src = &g_sv[sl][rbase];
            unsigned long long v[16];
            bool ok;
            do {
                // Issue all 16 loads back-to-back (max MLP), then check.
#pragma unroll
                for (int i = 0; i < 16; i++)
                    asm volatile("ld.relaxed.gpu.global.u64 %0, [%1];"
                                 : "=l"(v[i]) : "l"(src + i));
                unsigned bad = 0;
#pragma unroll
                for (int i = 0; i < 16; i++)
                    bad |= ((unsigned)(v[i] >> 32)) ^ ((unsigned)t);
                ok = (bad == 0);
            } while (!__all_sync(0xffffffffu, ok));
#pragma unroll
            for (int i = 0; i < 16; i++)
                sbuf[sb][rbase + i] = __uint_as_float((unsigned)v[i]);
        }
        __syncthreads();

        // Gate scalar m_{t-1}[j] for lane 0 (issue early, consumed late)
        float mj = 0.f;
        if (l == 0) mj = sbuf[sb][j];

        // 16 state rows from smem
        float mv[16];
        const float4* sp = (const float4*)&sbuf[sb][rbase];
#pragma unroll
        for (int i = 0; i < 4; i++) {
            float4 v4 = sp[i];
            mv[i * 4 + 0] = v4.x;
            mv[i * 4 + 1] = v4.y;
            mv[i * 4 + 2] = v4.z;
            mv[i * 4 + 3] = v4.w;
        }

        // Partial dot products, 4 accumulators per output to break FMA chains
        float az0 = 0.f, az1 = 0.f, az2 = 0.f, az3 = 0.f;
        float ah0 = 0.f, ah1 = 0.f, ah2 = 0.f, ah3 = 0.f;
#pragma unroll
        for (int i = 0; i < 4; i++) {
            az0 = fmaf(mv[i * 4 + 0], uz[i * 4 + 0], az0);
            az1 = fmaf(mv[i * 4 + 1], uz[i * 4 + 1], az1);
            az2 = fmaf(mv[i * 4 + 2], uz[i * 4 + 2], az2);
            az3 = fmaf(mv[i * 4 + 3], uz[i * 4 + 3], az3);
            ah0 = fmaf(mv[i * 4 + 0], uh[i * 4 + 0], ah0);
            ah1 = fmaf(mv[i * 4 + 1], uh[i * 4 + 1], ah1);
            ah2 = fmaf(mv[i * 4 + 2], uh[i * 4 + 2], ah2);
            ah3 = fmaf(mv[i * 4 + 3], uh[i * 4 + 3], ah3);
        }
        float az = (az0 + az1) + (az2 + az3);
        float ah = (ah0 + ah1) + (ah2 + ah3);

        // Butterfly reduce across the warp (column fully within this warp)
#pragma unroll
        for (int s = 16; s > 0; s >>= 1) {
            az += __shfl_xor_sync(0xffffffffu, az, s);
            ah += __shfl_xor_sync(0xffffffffu, ah, s);
        }

        if (l == 0) {
            float zp = az + xz;
            float hp = ah + xh;
            float z = __fdividef(1.f, 1.f + __expf(-zp));            // sigmoid
            float h = 1.f - __fdividef(2.f, __expf(2.f * hp) + 1.f); // tanh
            float mn = fmaf(z, h - mj, mj);
            unsigned long long pack =
                ((unsigned long long)(unsigned)(t + 1) << 32) |
                (unsigned long long)__float_as_uint(mn);
            asm volatile("st.relaxed.gpu.global.u64 [%0], %1;"
                         :: "l"(&g_sv[t & 1][j]), "l"(pack) : "memory");
            out[(size_t)t * F + j] = mn;
        }
        // No trailing __syncthreads: see header comment for the proof.
    }
}

// ---------------------------------------------------------------------------
// Launch: zero epochs -> GEMMs -> persistent scan. All graph-capturable.
// ---------------------------------------------------------------------------
extern "C" void kernel_launch(void* const* d_in, const int* in_sizes, int n_in,
                              void* d_out, int out_size)
{
    const float* x  = (const float*)d_in[0];
    const float* Wz = (const float*)d_in[1];
    const float* Uz = (const float*)d_in[2];
    const float* bz = (const float*)d_in[3];
    const float* Wh = (const float*)d_in[4];
    const float* Uh = (const float*)d_in[5];
    const float* bh = (const float*)d_in[6];
    float* out = (float*)d_out;

    zero_state_kernel<<<4, 256>>>();

    dim3 ggrid(F / BN, BATCH / BM, 2);   // 8 x 256 x 2
    gemm_kernel<<<ggrid, 256>>>(x, Wz, bz, Wh, bh);

    scan_kernel<<<NCTA, TPB>>>(Uz, Uh, out);
}

// round 4
// speedup vs baseline: 1.8480x; 1.8480x over previous
#include <cuda_runtime.h>
#include <cstdint>
#include <cstddef>

// Problem constants
#define BATCH 16384
#define F 512
#define NCTA 16          // scan CTAs; each owns 32 columns; all co-resident
#define TPB 512          // 16 warps; warp w owns columns b*32+w*2, +1

// Scratch (device globals: no allocation allowed in kernel_launch)
__device__ __align__(16) float g_xwz[(size_t)BATCH * F];   // x@Wz + bz
__device__ __align__(16) float g_xwh[(size_t)BATCH * F];   // x@Wh + bh
__device__ __align__(16) float g_m[2][F];                  // double-buffered state
__device__ unsigned g_flag[NCTA * 32];                     // 1 flag/CTA, 128B stride

// ---------------------------------------------------------------------------
// Zero the flags each launch (monotonic step counts; graph replays).
// ---------------------------------------------------------------------------
__global__ void zero_flags_kernel() {
    g_flag[threadIdx.x] = 0u;    // 512 words incl. padding
}

// ---------------------------------------------------------------------------
// Phase 1: batched GEMM  C = A(16384x512) * W(512x512) + bias
// blockIdx.z = 0 -> (Wz,bz)->g_xwz ; 1 -> (Wh,bh)->g_xwh
// ---------------------------------------------------------------------------
#define BM 64
#define BN 64
#define BKK 16

__global__ void __launch_bounds__(256) gemm_kernel(
    const float* __restrict__ A,
    const float* __restrict__ Wz, const float* __restrict__ bz,
    const float* __restrict__ Wh, const float* __restrict__ bh)
{
    const float* B    = (blockIdx.z == 0) ? Wz : Wh;
    const float* bias = (blockIdx.z == 0) ? bz : bh;
    float*       C    = (blockIdx.z == 0) ? g_xwz : g_xwh;

    __shared__ float As[BKK][BM];
    __shared__ float Bs[BKK][BN];

    const int row0 = blockIdx.y * BM;
    const int col0 = blockIdx.x * BN;
    const int tid  = threadIdx.x;

    const int a_m = tid >> 2;
    const int a_k = (tid & 3) * 4;
    const int b_k = tid >> 4;
    const int b_n = (tid & 15) * 4;

    const int ty = tid >> 4;
    const int tx = tid & 15;

    float acc[4][4] = {};

    for (int k0 = 0; k0 < F; k0 += BKK) {
        float4 av = *(const float4*)(A + (size_t)(row0 + a_m) * F + k0 + a_k);
        As[a_k + 0][a_m] = av.x;
        As[a_k + 1][a_m] = av.y;
        As[a_k + 2][a_m] = av.z;
        As[a_k + 3][a_m] = av.w;
        float4 bv = *(const float4*)(B + (size_t)(k0 + b_k) * F + col0 + b_n);
        *(float4*)&Bs[b_k][b_n] = bv;
        __syncthreads();
#pragma unroll
        for (int k = 0; k < BKK; k++) {
            float ar[4], br[4];
            *(float4*)ar = *(const float4*)&As[k][ty * 4];
            *(float4*)br = *(const float4*)&Bs[k][tx * 4];
#pragma unroll
            for (int i = 0; i < 4; i++)
#pragma unroll
                for (int jj = 0; jj < 4; jj++)
                    acc[i][jj] = fmaf(ar[i], br[jj], acc[i][jj]);
        }
        __syncthreads();
    }

    float4 bv;
    bv.x = __ldg(&bias[col0 + tx * 4 + 0]);
    bv.y = __ldg(&bias[col0 + tx * 4 + 1]);
    bv.z = __ldg(&bias[col0 + tx * 4 + 2]);
    bv.w = __ldg(&bias[col0 + tx * 4 + 3]);
#pragma unroll
    for (int i = 0; i < 4; i++) {
        float4 o;
        o.x = acc[i][0] + bv.x;
        o.y = acc[i][1] + bv.y;
        o.z = acc[i][2] + bv.z;
        o.w = acc[i][3] + bv.w;
        *(float4*)(C + (size_t)(row0 + ty * 4 + i) * F + col0 + tx * 4) = o;
    }
}

// ---------------------------------------------------------------------------
// Phase 2: sequential gated scan, 16 CTAs, per-CTA release-flag protocol.
//
// CTA b owns columns b*32 .. b*32+31. Warp w owns the column pair
// j0 = b*32 + w*2 (half-warp 0) and j0+1 (half-warp 1). Lane l handles
// column j0+(l>>4), state rows (l&15)*32 .. +31; it holds those 32 rows of
// Uz[:,col] and Uh[:,col] in registers (64 floats/thread, 2MB chip-wide).
//
// Protocol per step t:
//   - warp 0 polls the 16 per-CTA flags with ld.acquire.gpu until all >= t
//     (flag[c] = number of steps CTA c has published)
//   - __syncthreads (extends the acquire to the whole CTA)
//   - all threads __ldcg their 32 state rows from g_m[(t-1)&1], FMA against
//     register U, 4-level half-warp butterfly; lanes 0/16 apply the gate and
//     __stcg m_t[col] into g_m[t&1] and out
//   - __syncthreads; thread 0 publishes with ONE st.release.gpu (cumulative:
//     orders all warps' prior stores; no atomics, no membar)
//
// Overwrite safety for the double buffer: writing g_m[t&1] at step t clobbers
// m_{t-2}; this CTA reached step t only after its poll saw all flags >= t,
// i.e. every CTA published m_{t-1}, which (publish follows the post-read
// barrier) implies every CTA finished reading m_{t-2}.
// ---------------------------------------------------------------------------
__global__ void __launch_bounds__(TPB, 1) scan_kernel(
    const float* __restrict__ Uz,
    const float* __restrict__ Uh,
    float* __restrict__ out)
{
    const int b = blockIdx.x;
    const int w = threadIdx.x >> 5;
    const int l = threadIdx.x & 31;
    const int hw = l >> 4;                 // half-warp -> which column of pair
    const int hl = l & 15;                 // lane within half-warp
    const int mycol = b * 32 + w * 2 + hw; // global column 0..511
    const int rbase = hl * 32;             // first state row for this lane
    const bool head = (hl == 0);           // lanes 0 and 16: activation duty

    // Preload U slices into registers (64 floats/thread, one-time)
    float uz[32], uh[32];
#pragma unroll
    for (int i = 0; i < 32; i++) {
        uz[i] = Uz[(size_t)(rbase + i) * F + mycol];
        uh[i] = Uh[(size_t)(rbase + i) * F + mycol];
    }

    // ---- t = 0: m_prev = 0 ----
    if (head) {
        float xz = __ldg(&g_xwz[mycol]);
        float xh = __ldg(&g_xwh[mycol]);
        float z = __fdividef(1.f, 1.f + __expf(-xz));
        float h = 1.f - __fdividef(2.f, __expf(2.f * xh) + 1.f);
        float mn = z * h;
        __stcg(&g_m[0][mycol], mn);
        out[mycol] = mn;
    }
    __syncthreads();
    if (threadIdx.x == 0)
        asm volatile("st.release.gpu.global.u32 [%0], %1;"
                     :: "l"(&g_flag[b * 32]), "r"(1u) : "memory");

    for (int t = 1; t < BATCH; t++) {
        // Prefetch x@W terms (independent of recurrence; overlaps the poll)
        float xz = 0.f, xh = 0.f;
        if (head) {
            xz = __ldg(&g_xwz[(size_t)t * F + mycol]);
            xh = __ldg(&g_xwh[(size_t)t * F + mycol]);
        }

        // Warp 0 waits until every CTA has published step t-1
        if (w == 0) {
            const unsigned* fp = &g_flag[(l & 15) * 32];
            unsigned c;
            do {
                asm volatile("ld.acquire.gpu.global.u32 %0, [%1];"
                             : "=r"(c) : "l"(fp));
            } while (!__all_sync(0xffffffffu, c >= (unsigned)t));
        }
        __syncthreads();

        // Load 32 state rows (L2; L1 is stale for cross-SM data)
        const float* mprev = g_m[(t - 1) & 1];
        float mv[32];
        {
            const float4* mp = (const float4*)(mprev + rbase);
#pragma unroll
            for (int i = 0; i < 8; i++) {
                float4 v = __ldcg(mp + i);
                mv[i * 4 + 0] = v.x;
                mv[i * 4 + 1] = v.y;
                mv[i * 4 + 2] = v.z;
                mv[i * 4 + 3] = v.w;
            }
        }
        float mj = 0.f;
        if (head) mj = __ldcg(&mprev[mycol]);

        // Partial dots: 2 accumulators per gate to break FMA chains
        float az0 = 0.f, az1 = 0.f, ah0 = 0.f, ah1 = 0.f;
#pragma unroll
        for (int i = 0; i < 16; i++) {
            az0 = fmaf(mv[2 * i + 0], uz[2 * i + 0], az0);
            az1 = fmaf(mv[2 * i + 1], uz[2 * i + 1], az1);
            ah0 = fmaf(mv[2 * i + 0], uh[2 * i + 0], ah0);
            ah1 = fmaf(mv[2 * i + 1], uh[2 * i + 1], ah1);
        }
        float az = az0 + az1;
        float ah = ah0 + ah1;

        // 4-level butterfly within the half-warp (xor 8,4,2,1 stays inside)
#pragma unroll
        for (int s = 8; s > 0; s >>= 1) {
            az += __shfl_xor_sync(0xffffffffu, az, s);
            ah += __shfl_xor_sync(0xffffffffu, ah, s);
        }

        if (head) {
            float zp = az + xz;
            float hp = ah + xh;
            float z = __fdividef(1.f, 1.f + __expf(-zp));            // sigmoid
            float h = 1.f - __fdividef(2.f, __expf(2.f * hp) + 1.f); // tanh
            float mn = fmaf(z, h - mj, mj);
            __stcg(&g_m[t & 1][mycol], mn);
            out[(size_t)t * F + mycol] = mn;
        }

        __syncthreads();
        if (threadIdx.x == 0)
            asm volatile("st.release.gpu.global.u32 [%0], %1;"
                         :: "l"(&g_flag[b * 32]), "r"((unsigned)(t + 1))
                         : "memory");
    }
}

// ---------------------------------------------------------------------------
// Launch: zero flags -> GEMMs -> persistent scan. All graph-capturable.
// ---------------------------------------------------------------------------
extern "C" void kernel_launch(void* const* d_in, const int* in_sizes, int n_in,
                              void* d_out, int out_size)
{
    const float* x  = (const float*)d_in[0];
    const float* Wz = (const float*)d_in[1];
    const float* Uz = (const float*)d_in[2];
    const float* bz = (const float*)d_in[3];
    const float* Wh = (const float*)d_in[4];
    const float* Uh = (const float*)d_in[5];
    const float* bh = (const float*)d_in[6];
    float* out = (float*)d_out;

    zero_flags_kernel<<<1, NCTA * 32>>>();

    dim3 ggrid(F / BN, BATCH / BM, 2);   // 8 x 256 x 2
    gemm_kernel<<<ggrid, 256>>>(x, Wz, bz, Wh, bh);

    scan_kernel<<<NCTA, TPB>>>(Uz, Uh, out);
}

// round 5
// speedup vs baseline: 2.4891x; 1.3469x over previous
#include <cuda_runtime.h>
#include <cstdint>
#include <cstddef>

// Problem constants
#define BATCH 16384
#define F 512
#define CLUSTER 16       // one 16-CTA cluster (non-portable size), 1 GPC
#define TPB 512          // 16 warps; warp w owns columns b*32+2w, +1

// Scratch (device globals: no allocation allowed in kernel_launch)
__device__ __align__(16) float g_xwz[(size_t)BATCH * F];   // x@Wz + bz
__device__ __align__(16) float g_xwh[(size_t)BATCH * F];   // x@Wh + bh

// ---------------------------------------------------------------------------
// Small PTX helpers
// ---------------------------------------------------------------------------
__device__ __forceinline__ uint32_t smem_u32(const void* p) {
    uint32_t a;
    asm("{ .reg .u64 t; cvta.to.shared.u64 t, %1; cvt.u32.u64 %0, t; }"
        : "=r"(a) : "l"(p));
    return a;
}
__device__ __forceinline__ unsigned long long fma2(
    unsigned long long a, unsigned long long b, unsigned long long c) {
    unsigned long long d;
    asm("fma.rn.f32x2 %0, %1, %2, %3;" : "=l"(d) : "l"(a), "l"(b), "l"(c));
    return d;
}
__device__ __forceinline__ unsigned long long add2(
    unsigned long long a, unsigned long long b) {
    unsigned long long d;
    asm("add.rn.f32x2 %0, %1, %2;" : "=l"(d) : "l"(a), "l"(b));
    return d;
}
__device__ __forceinline__ float pair_sum(unsigned long long p) {
    uint32_t lo, hi;
    asm("mov.b64 {%0, %1}, %2;" : "=r"(lo), "=r"(hi) : "l"(p));
    return __uint_as_float(lo) + __uint_as_float(hi);
}
__device__ __forceinline__ unsigned long long pack2(float a0, float a1) {
    unsigned long long p;
    asm("mov.b64 %0, {%1, %2};" : "=l"(p)
        : "r"(__float_as_uint(a0)), "r"(__float_as_uint(a1)));
    return p;
}
// Store 4B into the smem of cluster CTA `rank` at this CTA's local address.
__device__ __forceinline__ void dsmem_store(uint32_t laddr, int rank, float v) {
    uint32_t raddr;
    asm volatile("mapa.shared::cluster.u32 %0, %1, %2;"
                 : "=r"(raddr) : "r"(laddr), "r"(rank));
    asm volatile("st.shared::cluster.f32 [%0], %1;"
                 :: "r"(raddr), "f"(v) : "memory");
}
__device__ __forceinline__ void cluster_arrive() {
    asm volatile("barrier.cluster.arrive.aligned;" ::: "memory");
}
__device__ __forceinline__ void cluster_wait() {
    asm volatile("barrier.cluster.wait.aligned;" ::: "memory");
}

// ---------------------------------------------------------------------------
// Phase 1: batched GEMM  C = A(16384x512) * W(512x512) + bias
// blockIdx.z = 0 -> (Wz,bz)->g_xwz ; 1 -> (Wh,bh)->g_xwh
// ---------------------------------------------------------------------------
#define BM 64
#define BN 64
#define BKK 16

__global__ void __launch_bounds__(256) gemm_kernel(
    const float* __restrict__ A,
    const float* __restrict__ Wz, const float* __restrict__ bz,
    const float* __restrict__ Wh, const float* __restrict__ bh)
{
    const float* B    = (blockIdx.z == 0) ? Wz : Wh;
    const float* bias = (blockIdx.z == 0) ? bz : bh;
    float*       C    = (blockIdx.z == 0) ? g_xwz : g_xwh;

    __shared__ float As[BKK][BM];
    __shared__ float Bs[BKK][BN];

    const int row0 = blockIdx.y * BM;
    const int col0 = blockIdx.x * BN;
    const int tid  = threadIdx.x;

    const int a_m = tid >> 2;
    const int a_k = (tid & 3) * 4;
    const int b_k = tid >> 4;
    const int b_n = (tid & 15) * 4;

    const int ty = tid >> 4;
    const int tx = tid & 15;

    float acc[4][4] = {};

    for (int k0 = 0; k0 < F; k0 += BKK) {
        float4 av = *(const float4*)(A + (size_t)(row0 + a_m) * F + k0 + a_k);
        As[a_k + 0][a_m] = av.x;
        As[a_k + 1][a_m] = av.y;
        As[a_k + 2][a_m] = av.z;
        As[a_k + 3][a_m] = av.w;
        float4 bv = *(const float4*)(B + (size_t)(k0 + b_k) * F + col0 + b_n);
        *(float4*)&Bs[b_k][b_n] = bv;
        __syncthreads();
#pragma unroll
        for (int k = 0; k < BKK; k++) {
            float ar[4], br[4];
            *(float4*)ar = *(const float4*)&As[k][ty * 4];
            *(float4*)br = *(const float4*)&Bs[k][tx * 4];
#pragma unroll
            for (int i = 0; i < 4; i++)
#pragma unroll
                for (int jj = 0; jj < 4; jj++)
                    acc[i][jj] = fmaf(ar[i], br[jj], acc[i][jj]);
        }
        __syncthreads();
    }

    float4 bv;
    bv.x = __ldg(&bias[col0 + tx * 4 + 0]);
    bv.y = __ldg(&bias[col0 + tx * 4 + 1]);
    bv.z = __ldg(&bias[col0 + tx * 4 + 2]);
    bv.w = __ldg(&bias[col0 + tx * 4 + 3]);
#pragma unroll
    for (int i = 0; i < 4; i++) {
        float4 o;
        o.x = acc[i][0] + bv.x;
        o.y = acc[i][1] + bv.y;
        o.z = acc[i][2] + bv.z;
        o.w = acc[i][3] + bv.w;
        *(float4*)(C + (size_t)(row0 + ty * 4 + i) * F + col0 + tx * 4) = o;
    }
}

// ---------------------------------------------------------------------------
// Phase 2: sequential gated scan as ONE 16-CTA cluster.
//
// CTA b (cluster rank b) owns columns b*32 .. b*32+31. Warp w owns the pair
// j0 = b*32 + 2w (half-warp 0) and j0+1 (half-warp 1). Lane l handles column
// j0+(l>>4), state rows (l&15)*32 .. +31; those 32 rows of Uz/Uh columns live
// in registers as 16+16 packed f32x2 words (2MB chip-wide, no reload).
//
// Per step t (sb = t&1, sbp = (t-1)&1):
//   - read m_{t-1} rows from LOCAL smem sbuf[sbp] (written by peers via DSMEM)
//   - 32 packed fma.rn.f32x2 against register U; 4-level half-warp butterfly
//     leaves the full dot product in EVERY lane
//   - head lane applies the gate (sigmoid/tanh), broadcasts m_t[col] via shfl
//   - lane hl stores m_t[col] into rank hl's sbuf[sb][col]  (16-way DSMEM
//     broadcast, one store per lane, no L2)
//   - head stores m_t[col] to out
//   - barrier.cluster.arrive (release: orders the DSMEM stores)
//   - prefetch x@W for step t+1 (overlaps the barrier)
//   - barrier.cluster.wait (acquire)
//
// Double-buffer safety: writing sbuf[sb] at step t clobbers m_{t-2}, whose
// last readers ran in step t-1 before that step's arrive; our writes happen
// after waiting on that same barrier. The cluster is gang-scheduled: no
// software spin anywhere -> no deadlock class.
// ---------------------------------------------------------------------------
__global__ void __launch_bounds__(TPB, 1) scan_kernel(
    const float* __restrict__ Uz,
    const float* __restrict__ Uh,
    float* __restrict__ out)
{
    __shared__ float sbuf[2][F];

    const int b = blockIdx.x;              // cluster rank (single cluster)
    const int w = threadIdx.x >> 5;
    const int l = threadIdx.x & 31;
    const int hw = l >> 4;                 // which column of the pair
    const int hl = l & 15;                 // lane within half-warp = target rank
    const int mycol = b * 32 + w * 2 + hw; // global column 0..511
    const int rbase = hl * 32;             // first state row for this lane
    const bool head = (hl == 0);

    // Preload packed U slices (rows rbase+2i, rbase+2i+1 of column mycol)
    unsigned long long uzp[16], uhp[16];
#pragma unroll
    for (int i = 0; i < 16; i++) {
        uzp[i] = pack2(Uz[(size_t)(rbase + 2 * i) * F + mycol],
                       Uz[(size_t)(rbase + 2 * i + 1) * F + mycol]);
        uhp[i] = pack2(Uh[(size_t)(rbase + 2 * i) * F + mycol],
                       Uh[(size_t)(rbase + 2 * i + 1) * F + mycol]);
    }

    const uint32_t sb_addr0 = smem_u32(&sbuf[0][mycol]);
    const uint32_t sb_addr1 = smem_u32(&sbuf[1][mycol]);

    // ---- t = 0: m_prev = 0 ----
    {
        float mn = 0.f;
        if (head) {
            float xz = __ldg(&g_xwz[mycol]);
            float xh = __ldg(&g_xwh[mycol]);
            float z = __fdividef(1.f, 1.f + __expf(-xz));
            float h = 1.f - __fdividef(2.f, __expf(2.f * xh) + 1.f);
            mn = z * h;
            out[mycol] = mn;
        }
        mn = __shfl_sync(0xffffffffu, mn, l & 16);
        dsmem_store(sb_addr0, hl, mn);
    }
    cluster_arrive();
    // Prefetch x@W for t = 1 while the barrier drains
    float xz_p = 0.f, xh_p = 0.f;
    if (head) {
        xz_p = __ldg(&g_xwz[F + mycol]);
        xh_p = __ldg(&g_xwh[F + mycol]);
    }
    cluster_wait();

    for (int t = 1; t < BATCH; t++) {
        const int sbp = (t - 1) & 1;
        const uint32_t dst = (t & 1) ? sb_addr1 : sb_addr0;

        // Gate scalar m_{t-1}[mycol] for the head lane (local LDS)
        float mj = 0.f;
        if (head) mj = sbuf[sbp][mycol];

        // 32 state rows as 16 packed f32x2 from local smem
        const unsigned long long* mp =
            (const unsigned long long*)&sbuf[sbp][rbase];

        unsigned long long az0 = 0ull, az1 = 0ull, ah0 = 0ull, ah1 = 0ull;
#pragma unroll
        for (int i = 0; i < 16; i += 2) {
            unsigned long long m0 = mp[i], m1 = mp[i + 1];
            az0 = fma2(m0, uzp[i], az0);
            az1 = fma2(m1, uzp[i + 1], az1);
            ah0 = fma2(m0, uhp[i], ah0);
            ah1 = fma2(m1, uhp[i + 1], ah1);
        }
        float az = pair_sum(add2(az0, az1));
        float ah = pair_sum(add2(ah0, ah1));

        // 4-level butterfly inside the half-warp: every lane gets the sum
#pragma unroll
        for (int s = 8; s > 0; s >>= 1) {
            az += __shfl_xor_sync(0xffffffffu, az, s);
            ah += __shfl_xor_sync(0xffffffffu, ah, s);
        }

        float mn = 0.f;
        if (head) {
            float zp = az + xz_p;
            float hp = ah + xh_p;
            float z = __fdividef(1.f, 1.f + __expf(-zp));            // sigmoid
            float h = 1.f - __fdividef(2.f, __expf(2.f * hp) + 1.f); // tanh
            mn = fmaf(z, h - mj, mj);
            out[(size_t)t * F + mycol] = mn;
        }
        mn = __shfl_sync(0xffffffffu, mn, l & 16);   // broadcast from head

        // 16-way DSMEM broadcast: lane hl -> rank hl, same column slot
        dsmem_store(dst, hl, mn);

        cluster_arrive();
        // Prefetch x@W for t+1 while the barrier drains
        if (head) {
            int tn = (t + 1 < BATCH) ? (t + 1) : t;
            xz_p = __ldg(&g_xwz[(size_t)tn * F + mycol]);
            xh_p = __ldg(&g_xwh[(size_t)tn * F + mycol]);
        }
        cluster_wait();
    }
}

// ---------------------------------------------------------------------------
// Launch: GEMMs -> single-cluster scan. All graph-capturable.
// ---------------------------------------------------------------------------
extern "C" void kernel_launch(void* const* d_in, const int* in_sizes, int n_in,
                              void* d_out, int out_size)
{
    const float* x  = (const float*)d_in[0];
    const float* Wz = (const float*)d_in[1];
    const float* Uz = (const float*)d_in[2];
    const float* bz = (const float*)d_in[3];
    const float* Wh = (const float*)d_in[4];
    const float* Uh = (const float*)d_in[5];
    const float* bh = (const float*)d_in[6];
    float* out = (float*)d_out;

    dim3 ggrid(F / BN, BATCH / BM, 2);   // 8 x 256 x 2
    gemm_kernel<<<ggrid, 256>>>(x, Wz, bz, Wh, bh);

    // Single 16-CTA cluster (non-portable size) for the scan
    cudaFuncSetAttribute(scan_kernel,
                         cudaFuncAttributeNonPortableClusterSizeAllowed, 1);
    cudaLaunchConfig_t cfg = {};
    cfg.gridDim  = dim3(CLUSTER, 1, 1);
    cfg.blockDim = dim3(TPB, 1, 1);
    cfg.dynamicSmemBytes = 0;
    cfg.stream = 0;
    cudaLaunchAttribute attrs[1];
    attrs[0].id = cudaLaunchAttributeClusterDimension;
    attrs[0].val.clusterDim.x = CLUSTER;
    attrs[0].val.clusterDim.y = 1;
    attrs[0].val.clusterDim.z = 1;
    cfg.attrs = attrs;
    cfg.numAttrs = 1;
    cudaLaunchKernelEx(&cfg, scan_kernel, Uz, Uh, out);
}